// round 9
// baseline (speedup 1.0000x reference)
#include <cuda_runtime.h>

#define N_ENT 50000
#define C 128
#define C4 (C / 4)
#define EPS 1e-12f

// Scratch (no allocation allowed): two ping-pong embedding/agg buffers + in-degree counts.
__device__ float g_bufA[(size_t)N_ENT * C];
__device__ float g_bufB[(size_t)N_ENT * C];
__device__ int   g_cnt[N_ENT];

// ---------------------------------------------------------------------------
// Zero a buffer (float4 vectorized); optionally also zero the count array.
// ---------------------------------------------------------------------------
__global__ void zero_kernel(float* __restrict__ buf, int n_float4, int zero_cnt) {
    int i = blockIdx.x * blockDim.x + threadIdx.x;
    int stride = gridDim.x * blockDim.x;
    float4 z = make_float4(0.f, 0.f, 0.f, 0.f);
    float4* b4 = reinterpret_cast<float4*>(buf);
    for (int j = i; j < n_float4; j += stride) b4[j] = z;
    if (zero_cnt) {
        for (int j = i; j < N_ENT; j += stride) g_cnt[j] = 0;
    }
}

// ---------------------------------------------------------------------------
// Scatter: one warp per edge. msg = emb_in[tail] * weight[edge_type-1];
// float4 reduction-atomic add into agg[head]. Optionally count in-degrees
// (hop 1 only; counts are identical across hops).
// NOTE: edge_index / edge_type are int32 (JAX x64-disabled downcasts int64).
// ---------------------------------------------------------------------------
template <bool COUNT>
__global__ void __launch_bounds__(256)
scatter_kernel(const float* __restrict__ emb_in,
               const int* __restrict__ edge_index,
               const int* __restrict__ edge_type,
               const float* __restrict__ weight,
               float* __restrict__ agg,
               int E) {
    int warp = (blockIdx.x * blockDim.x + threadIdx.x) >> 5;
    int lane = threadIdx.x & 31;
    if (warp >= E) return;

    int h = __ldg(&edge_index[warp]);       // head
    int t = __ldg(&edge_index[E + warp]);   // tail
    int r = __ldg(&edge_type[warp]) - 1;    // relation in [0, N_REL-2]

    const float4 v = __ldg(reinterpret_cast<const float4*>(emb_in + (size_t)t * C) + lane);
    const float4 w = __ldg(reinterpret_cast<const float4*>(weight + (size_t)r * C) + lane);
    float4 m = make_float4(v.x * w.x, v.y * w.y, v.z * w.z, v.w * w.w);

    atomicAdd(reinterpret_cast<float4*>(agg + (size_t)h * C) + lane, m);

    if (COUNT && lane == 0) {
        atomicAdd(&g_cnt[h], 1);
    }
}

// ---------------------------------------------------------------------------
// Finalize: one warp per entity row.
//   agg /= max(cnt,1); L2-normalize (eps=1e-12); store in-place (next hop input);
//   res += normalized.
// ---------------------------------------------------------------------------
__global__ void __launch_bounds__(256)
finalize_kernel(float* __restrict__ agg, float* __restrict__ res) {
    int row = (blockIdx.x * blockDim.x + threadIdx.x) >> 5;
    int lane = threadIdx.x & 31;
    if (row >= N_ENT) return;

    float4* arow = reinterpret_cast<float4*>(agg + (size_t)row * C);
    float4 a = arow[lane];

    float inv_d = 1.0f / fmaxf((float)g_cnt[row], 1.0f);
    a.x *= inv_d; a.y *= inv_d; a.z *= inv_d; a.w *= inv_d;

    float s = a.x * a.x + a.y * a.y + a.z * a.z + a.w * a.w;
    #pragma unroll
    for (int o = 16; o > 0; o >>= 1) s += __shfl_xor_sync(0xffffffff, s, o);

    float norm = sqrtf(s);
    float inv_n = 1.0f / fmaxf(norm, EPS);
    a.x *= inv_n; a.y *= inv_n; a.z *= inv_n; a.w *= inv_n;

    arow[lane] = a;  // in-place: becomes next hop's input embedding

    float4* rrow = reinterpret_cast<float4*>(res + (size_t)row * C);
    float4 o4 = rrow[lane];
    o4.x += a.x; o4.y += a.y; o4.z += a.z; o4.w += a.w;
    rrow[lane] = o4;
}

// ---------------------------------------------------------------------------
// kernel_launch
// Inputs (metadata order): entity_emb f32 [50000,128], edge_index i32 [2,E],
//                          edge_type i32 [E], weight f32 [10,128]
// Output: f32 [50000,128]
// ---------------------------------------------------------------------------
extern "C" void kernel_launch(void* const* d_in, const int* in_sizes, int n_in,
                              void* d_out, int out_size) {
    const float* emb = (const float*)d_in[0];
    const int*   ei  = (const int*)d_in[1];
    const int*   et  = (const int*)d_in[2];
    const float* w   = (const float*)d_in[3];
    float* out = (float*)d_out;

    const int E = in_sizes[1] / 2;
    const int NF4 = N_ENT * C / 4;

    void *pA = nullptr, *pB = nullptr;
    cudaGetSymbolAddress(&pA, g_bufA);
    cudaGetSymbolAddress(&pB, g_bufB);
    float* A = (float*)pA;
    float* B = (float*)pB;

    // res = entity_emb
    cudaMemcpyAsync(out, emb, (size_t)N_ENT * C * sizeof(float),
                    cudaMemcpyDeviceToDevice);

    const int SC_BLOCKS = (E + 7) / 8;          // 8 warps (edges) per 256-thread block
    const int FN_BLOCKS = (N_ENT + 7) / 8;      // 8 warps (rows) per block
    const int ZB = 1216;                        // ~8 blocks/SM for zeroing

    // Hop 1: agg in A, input = entity_emb, also compute counts
    zero_kernel<<<ZB, 256>>>(A, NF4, 1);
    scatter_kernel<true><<<SC_BLOCKS, 256>>>(emb, ei, et, w, A, E);
    finalize_kernel<<<FN_BLOCKS, 256>>>(A, out);

    // Hop 2: agg in B, input = A
    zero_kernel<<<ZB, 256>>>(B, NF4, 0);
    scatter_kernel<false><<<SC_BLOCKS, 256>>>(A, ei, et, w, B, E);
    finalize_kernel<<<FN_BLOCKS, 256>>>(B, out);

    // Hop 3: agg in A, input = B
    zero_kernel<<<ZB, 256>>>(A, NF4, 0);
    scatter_kernel<false><<<SC_BLOCKS, 256>>>(B, ei, et, w, A, E);
    finalize_kernel<<<FN_BLOCKS, 256>>>(A, out);
}

// round 11
// speedup vs baseline: 1.8156x; 1.8156x over previous
#include <cuda_runtime.h>

#define N_ENT  50000
#define C      128
#define E_MAX  1600000
#define N_RELM 10          // N_REL - 1
#define EPS    1e-12f

// Scratch (no allocation allowed).
__device__ float    g_bufA[(size_t)N_ENT * C];
__device__ float    g_bufB[(size_t)N_ENT * C];
__device__ int      g_cnt[N_ENT];
__device__ int      g_fill[N_ENT];
__device__ int      g_off[N_ENT + 1];
__device__ unsigned g_sorted[E_MAX];   // tail | (rel << 16)

// ---------------------------------------------------------------------------
// Zero the in-degree counters.
// ---------------------------------------------------------------------------
__global__ void zero_cnt_kernel() {
    int i = blockIdx.x * blockDim.x + threadIdx.x;
    if (i < N_ENT) g_cnt[i] = 0;
}

// ---------------------------------------------------------------------------
// Histogram of heads.
// ---------------------------------------------------------------------------
__global__ void hist_kernel(const int* __restrict__ edge_index, int E) {
    int e = blockIdx.x * blockDim.x + threadIdx.x;
    if (e < E) atomicAdd(&g_cnt[edge_index[e]], 1);
}

// ---------------------------------------------------------------------------
// Single-block exclusive scan over g_cnt -> g_off; also zeros g_fill.
// ---------------------------------------------------------------------------
__global__ void scan_kernel() {
    const int T = 1024;
    __shared__ int sh[T];
    int tid = threadIdx.x;
    const int chunk = (N_ENT + T - 1) / T;
    int begin = tid * chunk;
    int endi  = begin + chunk; if (endi > N_ENT) endi = N_ENT;
    if (begin > N_ENT) begin = N_ENT;

    int sum = 0;
    for (int i = begin; i < endi; i++) sum += g_cnt[i];
    sh[tid] = sum;
    __syncthreads();
    // Hillis-Steele inclusive scan
    for (int o = 1; o < T; o <<= 1) {
        int v = (tid >= o) ? sh[tid - o] : 0;
        __syncthreads();
        sh[tid] += v;
        __syncthreads();
    }
    int run = (tid == 0) ? 0 : sh[tid - 1];
    for (int i = begin; i < endi; i++) {
        g_off[i] = run;
        run += g_cnt[i];
        g_fill[i] = 0;
    }
    if (tid == T - 1) g_off[N_ENT] = run;   // == E
}

// ---------------------------------------------------------------------------
// Scatter edges into CSR order, packing (tail, rel) into one uint.
// tail < 65536 fits in 16 bits; rel in [0,9].
// ---------------------------------------------------------------------------
__global__ void build_kernel(const int* __restrict__ edge_index,
                             const int* __restrict__ edge_type, int E) {
    int e = blockIdx.x * blockDim.x + threadIdx.x;
    if (e >= E) return;
    int h = edge_index[e];
    unsigned t = (unsigned)edge_index[E + e];
    unsigned r = (unsigned)(edge_type[e] - 1);
    int pos = g_off[h] + atomicAdd(&g_fill[h], 1);
    g_sorted[pos] = t | (r << 16);
}

// ---------------------------------------------------------------------------
// One hop, fully fused: warp per head.
//   acc = sum over segment of emb_in[tail] * weight[rel]   (no atomics)
//   acc /= max(deg,1); L2-normalize; emb_out[h] = acc; res[h] += acc.
// ---------------------------------------------------------------------------
__global__ void __launch_bounds__(256)
hop_kernel(const float* __restrict__ emb_in,
           const float* __restrict__ weight,
           float* __restrict__ emb_out,
           float* __restrict__ res) {
    __shared__ float4 wsh[N_RELM * 32];   // 10 relations x 128 ch = 5 KB
    {
        float* wf = reinterpret_cast<float*>(wsh);
        for (int i = threadIdx.x; i < N_RELM * C; i += 256) wf[i] = weight[i];
    }
    __syncthreads();

    int head = blockIdx.x * 8 + (threadIdx.x >> 5);
    int lane = threadIdx.x & 31;
    if (head >= N_ENT) return;

    int start = g_off[head];
    int end   = g_off[head + 1];

    float4 acc = make_float4(0.f, 0.f, 0.f, 0.f);

    int e = start;
    // 4x unrolled main loop: MLP=4 on the 512B row gathers
    for (; e + 4 <= end; e += 4) {
        unsigned p0 = g_sorted[e + 0];
        unsigned p1 = g_sorted[e + 1];
        unsigned p2 = g_sorted[e + 2];
        unsigned p3 = g_sorted[e + 3];
        float4 v0 = __ldg(reinterpret_cast<const float4*>(emb_in + (size_t)(p0 & 0xFFFFu) * C) + lane);
        float4 v1 = __ldg(reinterpret_cast<const float4*>(emb_in + (size_t)(p1 & 0xFFFFu) * C) + lane);
        float4 v2 = __ldg(reinterpret_cast<const float4*>(emb_in + (size_t)(p2 & 0xFFFFu) * C) + lane);
        float4 v3 = __ldg(reinterpret_cast<const float4*>(emb_in + (size_t)(p3 & 0xFFFFu) * C) + lane);
        float4 w0 = wsh[(p0 >> 16) * 32 + lane];
        float4 w1 = wsh[(p1 >> 16) * 32 + lane];
        float4 w2 = wsh[(p2 >> 16) * 32 + lane];
        float4 w3 = wsh[(p3 >> 16) * 32 + lane];
        acc.x += v0.x * w0.x; acc.y += v0.y * w0.y; acc.z += v0.z * w0.z; acc.w += v0.w * w0.w;
        acc.x += v1.x * w1.x; acc.y += v1.y * w1.y; acc.z += v1.z * w1.z; acc.w += v1.w * w1.w;
        acc.x += v2.x * w2.x; acc.y += v2.y * w2.y; acc.z += v2.z * w2.z; acc.w += v2.w * w2.w;
        acc.x += v3.x * w3.x; acc.y += v3.y * w3.y; acc.z += v3.z * w3.z; acc.w += v3.w * w3.w;
    }
    for (; e < end; e++) {
        unsigned p = g_sorted[e];
        float4 v = __ldg(reinterpret_cast<const float4*>(emb_in + (size_t)(p & 0xFFFFu) * C) + lane);
        float4 w = wsh[(p >> 16) * 32 + lane];
        acc.x += v.x * w.x; acc.y += v.y * w.y; acc.z += v.z * w.z; acc.w += v.w * w.w;
    }

    // scatter_mean
    float inv_d = 1.0f / fmaxf((float)(end - start), 1.0f);
    acc.x *= inv_d; acc.y *= inv_d; acc.z *= inv_d; acc.w *= inv_d;

    // L2 normalize (per row)
    float s = acc.x * acc.x + acc.y * acc.y + acc.z * acc.z + acc.w * acc.w;
    #pragma unroll
    for (int o = 16; o > 0; o >>= 1) s += __shfl_xor_sync(0xffffffff, s, o);
    float inv_n = 1.0f / fmaxf(sqrtf(s), EPS);
    acc.x *= inv_n; acc.y *= inv_n; acc.z *= inv_n; acc.w *= inv_n;

    // next-hop input
    reinterpret_cast<float4*>(emb_out + (size_t)head * C)[lane] = acc;

    // res += normalized
    float4* rrow = reinterpret_cast<float4*>(res + (size_t)head * C);
    float4 o4 = rrow[lane];
    o4.x += acc.x; o4.y += acc.y; o4.z += acc.z; o4.w += acc.w;
    rrow[lane] = o4;
}

// ---------------------------------------------------------------------------
// kernel_launch
// Inputs: entity_emb f32 [50000,128], edge_index i32 [2,E],
//         edge_type i32 [E], weight f32 [10,128]
// Output: f32 [50000,128]
// ---------------------------------------------------------------------------
extern "C" void kernel_launch(void* const* d_in, const int* in_sizes, int n_in,
                              void* d_out, int out_size) {
    const float* emb = (const float*)d_in[0];
    const int*   ei  = (const int*)d_in[1];
    const int*   et  = (const int*)d_in[2];
    const float* w   = (const float*)d_in[3];
    float* out = (float*)d_out;

    const int E = in_sizes[1] / 2;

    void *pA = nullptr, *pB = nullptr;
    cudaGetSymbolAddress(&pA, g_bufA);
    cudaGetSymbolAddress(&pB, g_bufB);
    float* A = (float*)pA;
    float* B = (float*)pB;

    // res = entity_emb
    cudaMemcpyAsync(out, emb, (size_t)N_ENT * C * sizeof(float),
                    cudaMemcpyDeviceToDevice);

    // ---- Build CSR (once; reused by all 3 hops) ----
    zero_cnt_kernel<<<(N_ENT + 255) / 256, 256>>>();
    hist_kernel<<<(E + 255) / 256, 256>>>(ei, E);
    scan_kernel<<<1, 1024>>>();
    build_kernel<<<(E + 255) / 256, 256>>>(ei, et, E);

    // ---- 3 fused hops ----
    const int HOP_BLOCKS = (N_ENT + 7) / 8;   // warp per head, 8 warps/block
    hop_kernel<<<HOP_BLOCKS, 256>>>(emb, w, A, out);   // hop 1: in=entity_emb -> A
    hop_kernel<<<HOP_BLOCKS, 256>>>(A,   w, B, out);   // hop 2: A -> B
    hop_kernel<<<HOP_BLOCKS, 256>>>(B,   w, A, out);   // hop 3: B -> A (A unused after)
}